// round 9
// baseline (speedup 1.0000x reference)
#include <cuda_runtime.h>
#include <cstdint>

#define NBINS 64
#define ROW_LEN 8192
#define WARPS_PER_BLOCK 4          // 4 warps = 2 rows per block (2 warps/row)
#define ROWS_PER_BLOCK 2
#define BLOCK_THREADS (WARPS_PER_BLOCK * 32)
#define HALF_ROW (ROW_LEN / 2)     // 4096 elements per warp
#define VECS (HALF_ROW / 4 / 32)   // 32 float4 per lane

// R7's proven layout (u16 row-packing, bank = lane, per-warp-constant
// increment, provably conflict-free) with three chip-level changes:
//  - 128-thread CTAs: 16 blocks/SM (8 KB smem each, 2048-block grid in ONE
//    wave, capacity 148*16 = 2368). Halving the CTA work-quantum tightens
//    the per-CTA finish-time spread that sets single-wave duration.
//  - __ldcs evict-first loads: the 128 MB stream is touched once; keep it
//    from occupying L2.
//  - f32x2 packed add/mul (PTX): float4 halves are register-adjacent, so
//    packing is free; rn-per-half == scalar rn (bit-exact).
__global__ __launch_bounds__(BLOCK_THREADS, 16)
void hist_rows_kernel(const float* __restrict__ x, float* __restrict__ out) {
    __shared__ unsigned int priv[NBINS][32];

    const int warp   = threadIdx.x >> 5;
    const int lane   = threadIdx.x & 31;
    const int rowsel = warp >> 1;          // which row of the block's pair
    const int half   = warp & 1;           // which half of that row
    const int row    = blockIdx.x * ROWS_PER_BLOCK + rowsel;
    const unsigned int incr = rowsel ? 0x10000u : 1u;

    unsigned int* cell = &priv[0][0] + lane;   // bank = lane forever

    // Zero all counters (64*32 = 2048 words / 128 threads = 16 each).
    unsigned int* flat = &priv[0][0];
    #pragma unroll
    for (int i = 0; i < (NBINS * 32) / BLOCK_THREADS; i++)
        flat[threadIdx.x + i * BLOCK_THREADS] = 0u;
    __syncthreads();

    const float4* __restrict__ xr =
        (const float4*)(x + (size_t)row * ROW_LEN + (size_t)half * HALF_ROW) + lane;

    const float scale = 64.0f / 6.0f;   // NBINS / (VMAX - VMIN), fp32-rounded like ref
    // Packed operand replicas for f32x2 ops.
    uint64_t vmin2, scale2;
    {
        unsigned int c3 = __float_as_uint(3.0f);
        unsigned int cs = __float_as_uint(scale);
        asm("mov.b64 %0, {%1, %1};" : "=l"(vmin2)  : "r"(c3));
        asm("mov.b64 %0, {%1, %1};" : "=l"(scale2) : "r"(cs));
    }

    // Process one float4: two f32x2 (add then mul, rn per 32-bit half ==
    // reference scalar sequence), then per-element floor/clamp/atomic.
    #define PROC4(v)                                                          \
        do {                                                                  \
            uint64_t _a, _b;                                                  \
            asm("mov.b64 %0, {%1, %2};" : "=l"(_a)                            \
                : "r"(__float_as_uint((v).x)), "r"(__float_as_uint((v).y)));  \
            asm("mov.b64 %0, {%1, %2};" : "=l"(_b)                            \
                : "r"(__float_as_uint((v).z)), "r"(__float_as_uint((v).w)));  \
            asm("add.rn.f32x2 %0, %0, %1;" : "+l"(_a) : "l"(vmin2));          \
            asm("add.rn.f32x2 %0, %0, %1;" : "+l"(_b) : "l"(vmin2));          \
            asm("mul.rn.f32x2 %0, %0, %1;" : "+l"(_a) : "l"(scale2));         \
            asm("mul.rn.f32x2 %0, %0, %1;" : "+l"(_b) : "l"(scale2));         \
            unsigned int _r[4];                                               \
            asm("mov.b64 {%0, %1}, %2;" : "=r"(_r[0]), "=r"(_r[1]) : "l"(_a));\
            asm("mov.b64 {%0, %1}, %2;" : "=r"(_r[2]), "=r"(_r[3]) : "l"(_b));\
            _Pragma("unroll")                                                 \
            for (int _j = 0; _j < 4; _j++) {                                  \
                int _bn = __float2int_rd(__uint_as_float(_r[_j]));            \
                _bn = max(0, min(NBINS - 1, _bn));                            \
                atomicAdd(&cell[_bn * 32], incr);                             \
            }                                                                 \
        } while (0)

    // 32 float4 per lane, batches of 4 for MLP; evict-first streaming loads.
    #pragma unroll 1
    for (int it = 0; it < VECS; it += 4) {
        float4 v0 = __ldcs(&xr[(it + 0) * 32]);
        float4 v1 = __ldcs(&xr[(it + 1) * 32]);
        float4 v2 = __ldcs(&xr[(it + 2) * 32]);
        float4 v3 = __ldcs(&xr[(it + 3) * 32]);
        PROC4(v0);
        PROC4(v1);
        PROC4(v2);
        PROC4(v3);
    }
    #undef PROC4

    __syncthreads();

    // Reduce: each warp outputs 32 bins of ITS OWN row (half=0 -> bins [0,32),
    // half=1 -> [32,64)), extracting its row's u16 half. Rotated column
    // (t+lane)&31 keeps banks distinct per lane.
    const int bin = half * 32 + lane;
    const int shift = rowsel << 4;
    unsigned int s = 0;
    #pragma unroll
    for (int t = 0; t < 32; t++) {
        s += (priv[bin][(t + lane) & 31] >> shift) & 0xFFFFu;
    }

    const float inv_n = 1.0f / (float)ROW_LEN;
    out[(size_t)row * NBINS + bin] = (float)s * inv_n;
}

extern "C" void kernel_launch(void* const* d_in, const int* in_sizes, int n_in,
                              void* d_out, int out_size) {
    const float* x = (const float*)d_in[0];
    float* out = (float*)d_out;

    int nrows = in_sizes[0] / ROW_LEN;             // 4096
    int grid = nrows / ROWS_PER_BLOCK;             // 2048 blocks, single wave

    hist_rows_kernel<<<grid, BLOCK_THREADS>>>(x, out);
}